// round 4
// baseline (speedup 1.0000x reference)
#include <cuda_runtime.h>
#include <math.h>

#define FIN 128
#define HC 256            // H*C layer1 output width
#define NH 8              // heads layer 1
#define C2 32             // channels layer 2
#define GG 64             // graphs
#define NCLS 10
#define MAXN 100000
#define MAXE 1600000

// ---------------- scratch (device globals; no allocation allowed) ------------
__device__ float g_h1[MAXN * HC];          // x @ W1           (102.4 MB)
__device__ float g_out1[MAXN * HC];        // elu(gat1 + b1)   (102.4 MB)
__device__ float g_as1[MAXN * NH];
__device__ float g_ad1[MAXN * NH];
__device__ float g_h2[MAXN * C2];
__device__ float g_as2[MAXN];
__device__ float g_ad2[MAXN];
__device__ int   g_deg[MAXN];
__device__ int   g_rowptr[MAXN + 1];
__device__ int   g_cursor[MAXN];
__device__ int   g_csrc[MAXE];
__device__ int   g_bsum[128];
__device__ float g_pool[GG * C2];
__device__ float g_cnt[GG];

__device__ __forceinline__ float lrelu(float v) { return fmaxf(v, 0.2f * v); }

// ---- f32x2 packed-FMA helpers (FFMA2 only reachable via PTX on sm_103a) ----
__device__ __forceinline__ unsigned long long pk2(float lo, float hi) {
    unsigned long long r;
    asm("mov.b64 %0, {%1, %2};" : "=l"(r) : "f"(lo), "f"(hi));
    return r;
}
__device__ __forceinline__ void upk2(unsigned long long v, float& lo, float& hi) {
    asm("mov.b64 {%0, %1}, %2;" : "=f"(lo), "=f"(hi) : "l"(v));
}
__device__ __forceinline__ unsigned long long fma2(unsigned long long a,
                                                   unsigned long long b,
                                                   unsigned long long c) {
    unsigned long long d;
    asm("fma.rn.f32x2 %0, %1, %2, %3;" : "=l"(d) : "l"(a), "l"(b), "l"(c));
    return d;
}

// ---------------- init ------------------------------------------------------
__global__ void k_init(int n) {
    int g = blockIdx.x * blockDim.x + threadIdx.x;
    if (g < n) g_deg[g] = 0;
    if (g < GG * C2) g_pool[g] = 0.f;
    if (g < GG) g_cnt[g] = 0.f;
}

// ---------------- CSR build: histogram -> scan -> scatter -------------------
__global__ void k_hist(const int* __restrict__ ei, int E) {
    int e = blockIdx.x * blockDim.x + threadIdx.x;
    if (e < E) atomicAdd(&g_deg[ei[E + e]], 1);
}

__global__ void k_scan1(int n) {
    __shared__ int s[1024];
    int t = threadIdx.x;
    int g = blockIdx.x * 1024 + t;
    int v = (g < n) ? g_deg[g] : 0;
    s[t] = v;
    __syncthreads();
    for (int off = 1; off < 1024; off <<= 1) {
        int u = 0;
        if (t >= off) u = s[t - off];
        __syncthreads();
        if (t >= off) s[t] += u;
        __syncthreads();
    }
    if (g < n) g_rowptr[g] = s[t] - v;          // exclusive, chunk-local
    if (t == 1023) g_bsum[blockIdx.x] = s[1023];
}

__global__ void k_scan2(int nb) {              // single block, 128 threads
    __shared__ int s[128];
    int t = threadIdx.x;
    int v = (t < nb) ? g_bsum[t] : 0;
    s[t] = v;
    __syncthreads();
    for (int off = 1; off < 128; off <<= 1) {
        int u = 0;
        if (t >= off) u = s[t - off];
        __syncthreads();
        if (t >= off) s[t] += u;
        __syncthreads();
    }
    if (t < nb) g_bsum[t] = s[t] - v;          // exclusive
}

__global__ void k_scan3(int n, int E) {
    int g = blockIdx.x * 1024 + threadIdx.x;
    if (g < n) {
        int v = g_rowptr[g] + g_bsum[blockIdx.x];
        g_rowptr[g] = v;
        g_cursor[g] = v;
    }
    if (g == 0) g_rowptr[n] = E;
}

__global__ void k_scatter(const int* __restrict__ ei, int E) {
    int e = blockIdx.x * blockDim.x + threadIdx.x;
    if (e < E) {
        int s = ei[e];
        int d = ei[E + e];
        int pos = atomicAdd(&g_cursor[d], 1);
        g_csrc[pos] = s;
    }
}

// ---------------- GEMM1: h1 = x @ W1 via packed f32x2, + attention scores ---
// 256 threads = output columns; 32 nodes/block packed as 16 f32x2 node-pairs.
__global__ void k_gemm1(const float* __restrict__ x, const float* __restrict__ W1,
                        const float* __restrict__ asw, const float* __restrict__ adw,
                        int n) {
    __shared__ float xsT[FIN][34];             // [k][node], pad keeps 8B align
    int t = threadIdx.x;
    int n0 = blockIdx.x * 32;
    for (int idx = t; idx < 32 * FIN; idx += 256) {
        int j = idx >> 7, k = idx & 127;
        int nn = n0 + j;
        xsT[k][j] = (nn < n) ? x[nn * FIN + k] : 0.f;
    }
    __syncthreads();

    unsigned long long acc[16];
#pragma unroll
    for (int jp = 0; jp < 16; jp++) acc[jp] = 0ull;

#pragma unroll 4
    for (int k = 0; k < FIN; k++) {
        float w = W1[k * HC + t];
        unsigned long long w2 = pk2(w, w);
        const float* xr = &xsT[k][0];
#pragma unroll
        for (int jp = 0; jp < 16; jp++) {
            unsigned long long a2 = *(const unsigned long long*)(xr + 2 * jp);
            acc[jp] = fma2(a2, w2, acc[jp]);
        }
    }

    int lane = t & 31;
    int h = t >> 5;                // warp == head
    float aw = asw[t], dw = adw[t];
#pragma unroll
    for (int jp = 0; jp < 16; jp++) {
        float v0, v1;
        upk2(acc[jp], v0, v1);
#pragma unroll
        for (int half = 0; half < 2; half++) {
            int j = 2 * jp + half;
            float val = half ? v1 : v0;
            int nn = n0 + j;
            if (nn < n) g_h1[nn * HC + t] = val;
            float vs = val * aw, vd = val * dw;
#pragma unroll
            for (int off = 16; off; off >>= 1) {
                vs += __shfl_xor_sync(0xffffffffu, vs, off);
                vd += __shfl_xor_sync(0xffffffffu, vd, off);
            }
            if (lane == 0 && nn < n) {
                g_as1[nn * NH + h] = vs;
                g_ad1[nn * NH + h] = vd;
            }
        }
    }
}

// ---------------- GAT layer 1: warp/node, SINGLE fused pass (no max) --------
__global__ void k_gat1(const float* __restrict__ b1, int n) {
    int w = (blockIdx.x * blockDim.x + threadIdx.x) >> 5;
    int lane = threadIdx.x & 31;
    if (w >= n) return;
    int base = g_rowptr[w];
    int d = g_rowptr[w + 1] - base;

    float ad[NH], psf[NH];
    {
        float4 a0 = *(const float4*)&g_ad1[w * NH];
        float4 a1 = *(const float4*)&g_ad1[w * NH + 4];
        ad[0]=a0.x; ad[1]=a0.y; ad[2]=a0.z; ad[3]=a0.w;
        ad[4]=a1.x; ad[5]=a1.y; ad[6]=a1.z; ad[7]=a1.w;
        float4 s0 = *(const float4*)&g_as1[w * NH];
        float4 s1 = *(const float4*)&g_as1[w * NH + 4];
        float as_[NH] = {s0.x,s0.y,s0.z,s0.w,s1.x,s1.y,s1.z,s1.w};
#pragma unroll
        for (int h = 0; h < NH; h++) psf[h] = __expf(lrelu(as_[h] + ad[h]));
    }

    float acc[NH], z[NH];
#pragma unroll
    for (int h = 0; h < NH; h++) {
        acc[h] = psf[h] * g_h1[w * HC + h * 32 + lane];   // self-loop
        z[h] = 0.f;
    }

    for (int c0 = 0; c0 < d; c0 += 32) {
        int i = c0 + lane;
        int s = 0;
        float p[NH];
        if (i < d) {
            s = g_csrc[base + i];
            float4 a0 = *(const float4*)&g_as1[s * NH];
            float4 a1 = *(const float4*)&g_as1[s * NH + 4];
            float ae[NH] = {a0.x,a0.y,a0.z,a0.w,a1.x,a1.y,a1.z,a1.w};
#pragma unroll
            for (int h = 0; h < NH; h++) {
                p[h] = __expf(lrelu(ae[h] + ad[h]));
                z[h] += p[h];
            }
        } else {
#pragma unroll
            for (int h = 0; h < NH; h++) p[h] = 0.f;
        }
        int m = min(32, d - c0);
        for (int j = 0; j < m; j++) {
            int sj = __shfl_sync(0xffffffffu, s, j);
            const float* hp = &g_h1[sj * HC + lane];
#pragma unroll
            for (int h = 0; h < NH; h++)
                acc[h] += __shfl_sync(0xffffffffu, p[h], j) * hp[h * 32];
        }
    }

#pragma unroll
    for (int h = 0; h < NH; h++) {
#pragma unroll
        for (int off = 16; off; off >>= 1)
            z[h] += __shfl_xor_sync(0xffffffffu, z[h], off);
        z[h] += psf[h];
        float o = acc[h] / (z[h] + 1e-16f) + b1[h * 32 + lane];
        o = (o > 0.f) ? o : expm1f(o);                     // ELU
        g_out1[w * HC + h * 32 + lane] = o;
    }
}

// ---------------- GEMM2: h2 = out1 @ W2 via packed f32x2 (+ scores) ---------
// 256 threads = 8 warps; warp wi handles 4 nodes, full K; lane = out column.
__global__ void k_gemm2(const float* __restrict__ W2, const float* __restrict__ asw2,
                        const float* __restrict__ adw2, int n) {
    __shared__ float rsT[HC][34];              // [k][node]
    int t = threadIdx.x;
    int n0 = blockIdx.x * 32;
    for (int idx = t; idx < 32 * HC; idx += 256) {
        int j = idx >> 8, k = idx & 255;
        int nn = n0 + j;
        rsT[k][j] = (nn < n) ? g_out1[nn * HC + k] : 0.f;
    }
    __syncthreads();

    int lane = t & 31, wi = t >> 5;
    unsigned long long acc0 = 0ull, acc1 = 0ull;   // nodes 4wi+{0,1} and {2,3}
#pragma unroll 4
    for (int k = 0; k < HC; k++) {
        float wv = W2[k * C2 + lane];
        unsigned long long w2 = pk2(wv, wv);
        const float* xr = &rsT[k][4 * wi];
        unsigned long long a = *(const unsigned long long*)(xr);
        unsigned long long b = *(const unsigned long long*)(xr + 2);
        acc0 = fma2(a, w2, acc0);
        acc1 = fma2(b, w2, acc1);
    }

    float vals[4];
    upk2(acc0, vals[0], vals[1]);
    upk2(acc1, vals[2], vals[3]);
    float aw = asw2[lane], dw = adw2[lane];
#pragma unroll
    for (int j = 0; j < 4; j++) {
        int nn = n0 + 4 * wi + j;
        float vs = vals[j] * aw, vd = vals[j] * dw;
#pragma unroll
        for (int off = 16; off; off >>= 1) {
            vs += __shfl_xor_sync(0xffffffffu, vs, off);
            vd += __shfl_xor_sync(0xffffffffu, vd, off);
        }
        if (nn < n) {
            g_h2[nn * C2 + lane] = vals[j];
            if (lane == 0) { g_as2[nn] = vs; g_ad2[nn] = vd; }
        }
    }
}

// -------- GAT layer 2 (1 head), single fused pass (no max) + pooling --------
__global__ void k_gat2(const float* __restrict__ b2, const int* __restrict__ batch, int n) {
    int w = (blockIdx.x * blockDim.x + threadIdx.x) >> 5;
    int lane = threadIdx.x & 31;
    if (w >= n) return;
    int base = g_rowptr[w];
    int d = g_rowptr[w + 1] - base;
    float adn = g_ad2[w];
    float psf = __expf(lrelu(g_as2[w] + adn));
    float acc = psf * g_h2[w * C2 + lane];
    float z = 0.f;

    for (int c0 = 0; c0 < d; c0 += 32) {
        int i = c0 + lane;
        int s = 0;
        float p = 0.f;
        if (i < d) {
            s = g_csrc[base + i];
            p = __expf(lrelu(g_as2[s] + adn));
            z += p;
        }
        int m = min(32, d - c0);
        for (int j = 0; j < m; j++) {
            int sj = __shfl_sync(0xffffffffu, s, j);
            float pj = __shfl_sync(0xffffffffu, p, j);
            acc += pj * g_h2[sj * C2 + lane];
        }
    }
#pragma unroll
    for (int off = 16; off; off >>= 1)
        z += __shfl_xor_sync(0xffffffffu, z, off);
    z += psf;
    float val = acc / (z + 1e-16f) + b2[lane];
    int g = batch[w];
    atomicAdd(&g_pool[g * C2 + lane], val);
    if (lane == 0) atomicAdd(&g_cnt[g], 1.f);
}

// ---------------- final: mean-pool normalize + linear head ------------------
__global__ void k_final(const float* __restrict__ Wlin, const float* __restrict__ blin,
                        float* __restrict__ out) {
    int t = threadIdx.x;
    if (t >= GG * NCLS) return;
    int g = t / NCLS, c = t - g * NCLS;
    float inv = 1.f / fmaxf(g_cnt[g], 1.f);
    float acc = blin[c];
#pragma unroll
    for (int k = 0; k < C2; k++)
        acc += g_pool[g * C2 + k] * inv * Wlin[k * NCLS + c];
    out[t] = acc;
}

// ---------------- launch ----------------------------------------------------
extern "C" void kernel_launch(void* const* d_in, const int* in_sizes, int n_in,
                              void* d_out, int out_size) {
    const float* x    = (const float*)d_in[0];
    const int*   ei   = (const int*)d_in[1];
    const int*   batch= (const int*)d_in[2];
    const float* W1   = (const float*)d_in[3];
    const float* asw1 = (const float*)d_in[4];
    const float* adw1 = (const float*)d_in[5];
    const float* b1   = (const float*)d_in[6];
    const float* W2   = (const float*)d_in[7];
    const float* asw2 = (const float*)d_in[8];
    const float* adw2 = (const float*)d_in[9];
    const float* b2   = (const float*)d_in[10];
    const float* Wlin = (const float*)d_in[11];
    const float* blin = (const float*)d_in[12];
    float* out = (float*)d_out;

    int n = in_sizes[0] / FIN;
    int E = in_sizes[1] / 2;
    int nb = (n + 1023) / 1024;

    k_init<<<(n + 255) / 256, 256>>>(n);
    k_hist<<<(E + 255) / 256, 256>>>(ei, E);
    k_scan1<<<nb, 1024>>>(n);
    k_scan2<<<1, 128>>>(nb);
    k_scan3<<<nb, 1024>>>(n, E);
    k_scatter<<<(E + 255) / 256, 256>>>(ei, E);
    k_gemm1<<<(n + 31) / 32, 256>>>(x, W1, asw1, adw1, n);
    k_gat1<<<(n + 7) / 8, 256>>>(b1, n);
    k_gemm2<<<(n + 31) / 32, 256>>>(W2, asw2, adw2, n);
    k_gat2<<<(n + 7) / 8, 256>>>(b2, batch, n);
    k_final<<<1, GG * NCLS>>>(Wlin, blin, out);
}

// round 5
// speedup vs baseline: 1.5742x; 1.5742x over previous
#include <cuda_runtime.h>
#include <cuda_bf16.h>
#include <math.h>

#define FIN 128
#define HC 256            // H*C layer1 output width
#define NH 8              // heads layer 1
#define C2 32             // channels layer 2
#define GG 64             // graphs
#define NCLS 10
#define MAXN 100000
#define MAXE 1600000

// ---------------- scratch (device globals; no allocation allowed) ------------
__device__ __align__(16) unsigned g_h1b[MAXN * (HC / 2)];  // bf16x2 h1 (51.2 MB)
__device__ float g_out1[MAXN * HC];        // elu(gat1 + b1)   (102.4 MB)
__device__ float g_as1[MAXN * NH];
__device__ float g_ad1[MAXN * NH];
__device__ float g_h2[MAXN * C2];
__device__ float g_as2[MAXN];
__device__ float g_ad2[MAXN];
__device__ int   g_deg[MAXN];
__device__ int   g_rowptr[MAXN + 1];
__device__ int   g_cursor[MAXN];
__device__ int   g_csrc[MAXE];
__device__ int   g_bsum[128];
__device__ float g_pool[GG * C2];
__device__ float g_cnt[GG];

__device__ __forceinline__ float lrelu(float v) { return fmaxf(v, 0.2f * v); }

// ---- f32x2 packed-FMA helpers (FFMA2 only reachable via PTX on sm_103a) ----
__device__ __forceinline__ unsigned long long pk2(float lo, float hi) {
    unsigned long long r;
    asm("mov.b64 %0, {%1, %2};" : "=l"(r) : "f"(lo), "f"(hi));
    return r;
}
__device__ __forceinline__ void upk2(unsigned long long v, float& lo, float& hi) {
    asm("mov.b64 {%0, %1}, %2;" : "=f"(lo), "=f"(hi) : "l"(v));
}
__device__ __forceinline__ unsigned long long fma2(unsigned long long a,
                                                   unsigned long long b,
                                                   unsigned long long c) {
    unsigned long long d;
    asm("fma.rn.f32x2 %0, %1, %2, %3;" : "=l"(d) : "l"(a), "l"(b), "l"(c));
    return d;
}
__device__ __forceinline__ unsigned bfpack(float a, float b) {
    __nv_bfloat162 t = __floats2bfloat162_rn(a, b);
    return *reinterpret_cast<unsigned*>(&t);
}
__device__ __forceinline__ float2 bfun(unsigned u) {
    __nv_bfloat162 t = *reinterpret_cast<__nv_bfloat162*>(&u);
    return __bfloat1622float2(t);
}

// ---------------- init ------------------------------------------------------
__global__ void k_init(int n) {
    int g = blockIdx.x * blockDim.x + threadIdx.x;
    if (g < n) g_deg[g] = 0;
    if (g < GG * C2) g_pool[g] = 0.f;
    if (g < GG) g_cnt[g] = 0.f;
}

// ---------------- CSR build: histogram -> scan -> scatter -------------------
__global__ void k_hist(const int* __restrict__ ei, int E) {
    int e = blockIdx.x * blockDim.x + threadIdx.x;
    if (e < E) atomicAdd(&g_deg[ei[E + e]], 1);
}

__global__ void k_scan1(int n) {
    __shared__ int s[1024];
    int t = threadIdx.x;
    int g = blockIdx.x * 1024 + t;
    int v = (g < n) ? g_deg[g] : 0;
    s[t] = v;
    __syncthreads();
    for (int off = 1; off < 1024; off <<= 1) {
        int u = 0;
        if (t >= off) u = s[t - off];
        __syncthreads();
        if (t >= off) s[t] += u;
        __syncthreads();
    }
    if (g < n) g_rowptr[g] = s[t] - v;          // exclusive, chunk-local
    if (t == 1023) g_bsum[blockIdx.x] = s[1023];
}

__global__ void k_scan2(int nb) {              // single block, 128 threads
    __shared__ int s[128];
    int t = threadIdx.x;
    int v = (t < nb) ? g_bsum[t] : 0;
    s[t] = v;
    __syncthreads();
    for (int off = 1; off < 128; off <<= 1) {
        int u = 0;
        if (t >= off) u = s[t - off];
        __syncthreads();
        if (t >= off) s[t] += u;
        __syncthreads();
    }
    if (t < nb) g_bsum[t] = s[t] - v;          // exclusive
}

__global__ void k_scan3(int n, int E) {
    int g = blockIdx.x * 1024 + threadIdx.x;
    if (g < n) {
        int v = g_rowptr[g] + g_bsum[blockIdx.x];
        g_rowptr[g] = v;
        g_cursor[g] = v;
    }
    if (g == 0) g_rowptr[n] = E;
}

__global__ void k_scatter(const int* __restrict__ ei, int E) {
    int e = blockIdx.x * blockDim.x + threadIdx.x;
    if (e < E) {
        int s = ei[e];
        int d = ei[E + e];
        int pos = atomicAdd(&g_cursor[d], 1);
        g_csrc[pos] = s;
    }
}

// ---------------- GEMM1: register-tiled h1 = x @ W1 + scores ----------------
// Block: 256 threads, tile 64 nodes x 256 cols, K=128 in chunks of 16.
// Warp ty owns nodes 8ty..8ty+7; lane tx owns cols 8tx..8tx+7 (head = tx/4).
// Thread tile 8x8: per k -> 8 broadcast LDS (A) + 2 LDS.128 (B) + 32 FFMA2.
__global__ void k_gemm1(const float* __restrict__ x, const float* __restrict__ W1,
                        const float* __restrict__ asw, const float* __restrict__ adw,
                        int n) {
    __shared__ float xs[64][FIN];       // 32 KB
    __shared__ float ws[16][HC];        // 16 KB
    int t = threadIdx.x;
    int tx = t & 31, ty = t >> 5;
    int n0 = blockIdx.x * 64;

    for (int idx = t; idx < 64 * (FIN / 4); idx += 256) {
        int nn = idx >> 5, c4 = (idx & 31) << 2;
        float4 v = make_float4(0.f, 0.f, 0.f, 0.f);
        if (n0 + nn < n) v = *(const float4*)&x[(n0 + nn) * FIN + c4];
        *(float4*)&xs[nn][c4] = v;
    }

    unsigned long long acc[8][4];
#pragma unroll
    for (int j = 0; j < 8; j++)
#pragma unroll
        for (int cp = 0; cp < 4; cp++) acc[j][cp] = 0ull;

    for (int kc = 0; kc < FIN / 16; kc++) {
        __syncthreads();
        for (int idx = t; idx < 16 * (HC / 4); idx += 256) {
            int kk = idx >> 6, c4 = (idx & 63) << 2;
            *(float4*)&ws[kk][c4] = *(const float4*)&W1[(kc * 16 + kk) * HC + c4];
        }
        __syncthreads();
#pragma unroll
        for (int kk = 0; kk < 16; kk++) {
            int k = kc * 16 + kk;
            float4 b0 = *(const float4*)&ws[kk][8 * tx];
            float4 b1v = *(const float4*)&ws[kk][8 * tx + 4];
            unsigned long long bp[4];
            bp[0] = pk2(b0.x, b0.y);  bp[1] = pk2(b0.z, b0.w);
            bp[2] = pk2(b1v.x, b1v.y); bp[3] = pk2(b1v.z, b1v.w);
#pragma unroll
            for (int j = 0; j < 8; j++) {
                float a = xs[8 * ty + j][k];
                unsigned long long a2 = pk2(a, a);
                acc[j][0] = fma2(a2, bp[0], acc[j][0]);
                acc[j][1] = fma2(a2, bp[1], acc[j][1]);
                acc[j][2] = fma2(a2, bp[2], acc[j][2]);
                acc[j][3] = fma2(a2, bp[3], acc[j][3]);
            }
        }
    }

    float aswv[8], adwv[8];
    {
        float4 s0 = *(const float4*)&asw[8 * tx];
        float4 s1 = *(const float4*)&asw[8 * tx + 4];
        float4 d0 = *(const float4*)&adw[8 * tx];
        float4 d1 = *(const float4*)&adw[8 * tx + 4];
        aswv[0]=s0.x; aswv[1]=s0.y; aswv[2]=s0.z; aswv[3]=s0.w;
        aswv[4]=s1.x; aswv[5]=s1.y; aswv[6]=s1.z; aswv[7]=s1.w;
        adwv[0]=d0.x; adwv[1]=d0.y; adwv[2]=d0.z; adwv[3]=d0.w;
        adwv[4]=d1.x; adwv[5]=d1.y; adwv[6]=d1.z; adwv[7]=d1.w;
    }

#pragma unroll
    for (int j = 0; j < 8; j++) {
        int nn = n0 + 8 * ty + j;
        float v[8];
        upk2(acc[j][0], v[0], v[1]); upk2(acc[j][1], v[2], v[3]);
        upk2(acc[j][2], v[4], v[5]); upk2(acc[j][3], v[6], v[7]);
        // bf16 pack + store
        if (nn < n) {
            uint4 pkd;
            pkd.x = bfpack(v[0], v[1]); pkd.y = bfpack(v[2], v[3]);
            pkd.z = bfpack(v[4], v[5]); pkd.w = bfpack(v[6], v[7]);
            *(uint4*)&g_h1b[nn * (HC / 2) + 4 * tx] = pkd;
        }
        // attention score partials (all 8 cols in head tx/4)
        float vs = 0.f, vd = 0.f;
#pragma unroll
        for (int c = 0; c < 8; c++) { vs += v[c] * aswv[c]; vd += v[c] * adwv[c]; }
        vs += __shfl_xor_sync(0xffffffffu, vs, 1);
        vs += __shfl_xor_sync(0xffffffffu, vs, 2);
        vd += __shfl_xor_sync(0xffffffffu, vd, 1);
        vd += __shfl_xor_sync(0xffffffffu, vd, 2);
        if ((tx & 3) == 0 && nn < n) {
            g_as1[nn * NH + (tx >> 2)] = vs;
            g_ad1[nn * NH + (tx >> 2)] = vd;
        }
    }
}

// ---------------- GAT layer 1: warp/node, fused pass, bf16 gather -----------
// Lane owns channels 8*lane..8*lane+7 (head = lane/4). p broadcast via smem.
__global__ void k_gat1(const float* __restrict__ b1, int n) {
    __shared__ float ps[8][32 * 9];
    int w = (blockIdx.x * blockDim.x + threadIdx.x) >> 5;
    int lane = threadIdx.x & 31;
    int wl = (threadIdx.x >> 5);
    if (w >= n) return;
    int base = g_rowptr[w];
    int d = g_rowptr[w + 1] - base;
    int h_me = lane >> 2;

    float ad[NH];
    {
        float4 a0 = *(const float4*)&g_ad1[w * NH];
        float4 a1 = *(const float4*)&g_ad1[w * NH + 4];
        ad[0]=a0.x; ad[1]=a0.y; ad[2]=a0.z; ad[3]=a0.w;
        ad[4]=a1.x; ad[5]=a1.y; ad[6]=a1.z; ad[7]=a1.w;
    }
    float psf = __expf(lrelu(g_as1[w * NH + h_me] + ad[h_me]));

    float acc[8];
    {
        uint4 hv = *(const uint4*)&g_h1b[w * (HC / 2) + 4 * lane];
        float2 f0 = bfun(hv.x), f1 = bfun(hv.y), f2 = bfun(hv.z), f3 = bfun(hv.w);
        acc[0] = psf * f0.x; acc[1] = psf * f0.y;
        acc[2] = psf * f1.x; acc[3] = psf * f1.y;
        acc[4] = psf * f2.x; acc[5] = psf * f2.y;
        acc[6] = psf * f3.x; acc[7] = psf * f3.y;
    }
    float z = 0.f;   // sum of p over all edges for MY head (accumulated on read)

    for (int c0 = 0; c0 < d; c0 += 32) {
        int i = c0 + lane;
        int s = 0;
        float p[NH];
#pragma unroll
        for (int h = 0; h < NH; h++) p[h] = 0.f;
        if (i < d) {
            s = g_csrc[base + i];
            float4 e0 = *(const float4*)&g_as1[s * NH];
            float4 e1 = *(const float4*)&g_as1[s * NH + 4];
            float ae[NH] = {e0.x, e0.y, e0.z, e0.w, e1.x, e1.y, e1.z, e1.w};
#pragma unroll
            for (int h = 0; h < NH; h++) p[h] = __expf(lrelu(ae[h] + ad[h]));
        }
#pragma unroll
        for (int h = 0; h < NH; h++) ps[wl][lane * 9 + h] = p[h];
        __syncwarp();

        int m = min(32, d - c0);
        for (int j = 0; j < m; j++) {
            int sj = __shfl_sync(0xffffffffu, s, j);
            float pj = ps[wl][j * 9 + h_me];
            z += pj;
            uint4 hv = *(const uint4*)&g_h1b[sj * (HC / 2) + 4 * lane];
            float2 f0 = bfun(hv.x), f1 = bfun(hv.y), f2 = bfun(hv.z), f3 = bfun(hv.w);
            acc[0] += pj * f0.x; acc[1] += pj * f0.y;
            acc[2] += pj * f1.x; acc[3] += pj * f1.y;
            acc[4] += pj * f2.x; acc[5] += pj * f2.y;
            acc[6] += pj * f3.x; acc[7] += pj * f3.y;
        }
        __syncwarp();
    }

    z += psf;
    float invz = 1.f / (z + 1e-16f);
    float4 bb0 = *(const float4*)&b1[8 * lane];
    float4 bb1 = *(const float4*)&b1[8 * lane + 4];
    float bv[8] = {bb0.x, bb0.y, bb0.z, bb0.w, bb1.x, bb1.y, bb1.z, bb1.w};
    float o[8];
#pragma unroll
    for (int c = 0; c < 8; c++) {
        float v = acc[c] * invz + bv[c];
        o[c] = (v > 0.f) ? v : expm1f(v);               // ELU
    }
    *(float4*)&g_out1[w * HC + 8 * lane]     = make_float4(o[0], o[1], o[2], o[3]);
    *(float4*)&g_out1[w * HC + 8 * lane + 4] = make_float4(o[4], o[5], o[6], o[7]);
}

// ---------------- GEMM2: register-tiled h2 = out1 @ W2 (+ scores) -----------
// Block 256 threads, tile 128 nodes x 32 cols, K=256 in chunks of 16.
// tx = t%8 -> cols 4tx..4tx+3 ; ty = t/8 -> nodes 4ty..4ty+3.
__global__ void k_gemm2(const float* __restrict__ W2, const float* __restrict__ asw2,
                        const float* __restrict__ adw2, int n) {
    __shared__ float ws2[HC][C2];       // 32 KB, loaded once
    __shared__ float xs[128][24];       // 12 KB per 16-k chunk
    int t = threadIdx.x;
    int tx = t & 7, ty = t >> 3;
    int n0 = blockIdx.x * 128;

    for (int idx = t; idx < HC * (C2 / 4); idx += 256) {
        int kk = idx >> 3, c4 = (idx & 7) << 2;
        *(float4*)&ws2[kk][c4] = *(const float4*)&W2[kk * C2 + c4];
    }

    unsigned long long acc[4][2];
#pragma unroll
    for (int j = 0; j < 4; j++) { acc[j][0] = 0ull; acc[j][1] = 0ull; }

    for (int kc = 0; kc < HC / 16; kc++) {
        __syncthreads();
        for (int idx = t; idx < 128 * 4; idx += 256) {
            int nn = idx >> 2, c4 = (idx & 3) << 2;
            float4 v = make_float4(0.f, 0.f, 0.f, 0.f);
            if (n0 + nn < n) v = *(const float4*)&g_out1[(n0 + nn) * HC + kc * 16 + c4];
            *(float4*)&xs[nn][c4] = v;
        }
        __syncthreads();
#pragma unroll
        for (int kk = 0; kk < 16; kk++) {
            float4 bw = *(const float4*)&ws2[kc * 16 + kk][4 * tx];
            unsigned long long bp0 = pk2(bw.x, bw.y);
            unsigned long long bp1 = pk2(bw.z, bw.w);
#pragma unroll
            for (int j = 0; j < 4; j++) {
                float a = xs[4 * ty + j][kk];
                unsigned long long a2 = pk2(a, a);
                acc[j][0] = fma2(a2, bp0, acc[j][0]);
                acc[j][1] = fma2(a2, bp1, acc[j][1]);
            }
        }
    }

    float aswv[4], adwv[4];
    {
        float4 s0 = *(const float4*)&asw2[4 * tx];
        float4 d0 = *(const float4*)&adw2[4 * tx];
        aswv[0]=s0.x; aswv[1]=s0.y; aswv[2]=s0.z; aswv[3]=s0.w;
        adwv[0]=d0.x; adwv[1]=d0.y; adwv[2]=d0.z; adwv[3]=d0.w;
    }
#pragma unroll
    for (int j = 0; j < 4; j++) {
        int nn = n0 + 4 * ty + j;
        float v[4];
        upk2(acc[j][0], v[0], v[1]);
        upk2(acc[j][1], v[2], v[3]);
        if (nn < n)
            *(float4*)&g_h2[nn * C2 + 4 * tx] = make_float4(v[0], v[1], v[2], v[3]);
        float vs = 0.f, vd = 0.f;
#pragma unroll
        for (int c = 0; c < 4; c++) { vs += v[c] * aswv[c]; vd += v[c] * adwv[c]; }
        vs += __shfl_xor_sync(0xffffffffu, vs, 1);
        vs += __shfl_xor_sync(0xffffffffu, vs, 2);
        vs += __shfl_xor_sync(0xffffffffu, vs, 4);
        vd += __shfl_xor_sync(0xffffffffu, vd, 1);
        vd += __shfl_xor_sync(0xffffffffu, vd, 2);
        vd += __shfl_xor_sync(0xffffffffu, vd, 4);
        if (tx == 0 && nn < n) { g_as2[nn] = vs; g_ad2[nn] = vd; }
    }
}

// -------- GAT layer 2 (1 head), single fused pass (no max) + pooling --------
__global__ void k_gat2(const float* __restrict__ b2, const int* __restrict__ batch, int n) {
    int w = (blockIdx.x * blockDim.x + threadIdx.x) >> 5;
    int lane = threadIdx.x & 31;
    if (w >= n) return;
    int base = g_rowptr[w];
    int d = g_rowptr[w + 1] - base;
    float adn = g_ad2[w];
    float psf = __expf(lrelu(g_as2[w] + adn));
    float acc = psf * g_h2[w * C2 + lane];
    float z = 0.f;

    for (int c0 = 0; c0 < d; c0 += 32) {
        int i = c0 + lane;
        int s = 0;
        float p = 0.f;
        if (i < d) {
            s = g_csrc[base + i];
            p = __expf(lrelu(g_as2[s] + adn));
            z += p;
        }
        int m = min(32, d - c0);
        for (int j = 0; j < m; j++) {
            int sj = __shfl_sync(0xffffffffu, s, j);
            float pj = __shfl_sync(0xffffffffu, p, j);
            acc += pj * g_h2[sj * C2 + lane];
        }
    }
#pragma unroll
    for (int off = 16; off; off >>= 1)
        z += __shfl_xor_sync(0xffffffffu, z, off);
    z += psf;
    float val = acc / (z + 1e-16f) + b2[lane];
    int g = batch[w];
    atomicAdd(&g_pool[g * C2 + lane], val);
    if (lane == 0) atomicAdd(&g_cnt[g], 1.f);
}

// ---------------- final: mean-pool normalize + linear head ------------------
__global__ void k_final(const float* __restrict__ Wlin, const float* __restrict__ blin,
                        float* __restrict__ out) {
    int t = threadIdx.x;
    if (t >= GG * NCLS) return;
    int g = t / NCLS, c = t - g * NCLS;
    float inv = 1.f / fmaxf(g_cnt[g], 1.f);
    float acc = blin[c];
#pragma unroll
    for (int k = 0; k < C2; k++)
        acc += g_pool[g * C2 + k] * inv * Wlin[k * NCLS + c];
    out[t] = acc;
}

// ---------------- launch ----------------------------------------------------
extern "C" void kernel_launch(void* const* d_in, const int* in_sizes, int n_in,
                              void* d_out, int out_size) {
    const float* x    = (const float*)d_in[0];
    const int*   ei   = (const int*)d_in[1];
    const int*   batch= (const int*)d_in[2];
    const float* W1   = (const float*)d_in[3];
    const float* asw1 = (const float*)d_in[4];
    const float* adw1 = (const float*)d_in[5];
    const float* b1   = (const float*)d_in[6];
    const float* W2   = (const float*)d_in[7];
    const float* asw2 = (const float*)d_in[8];
    const float* adw2 = (const float*)d_in[9];
    const float* b2   = (const float*)d_in[10];
    const float* Wlin = (const float*)d_in[11];
    const float* blin = (const float*)d_in[12];
    float* out = (float*)d_out;

    int n = in_sizes[0] / FIN;
    int E = in_sizes[1] / 2;
    int nb = (n + 1023) / 1024;

    k_init<<<(n + 255) / 256, 256>>>(n);
    k_hist<<<(E + 255) / 256, 256>>>(ei, E);
    k_scan1<<<nb, 1024>>>(n);
    k_scan2<<<1, 128>>>(nb);
    k_scan3<<<nb, 1024>>>(n, E);
    k_scatter<<<(E + 255) / 256, 256>>>(ei, E);
    k_gemm1<<<(n + 63) / 64, 256>>>(x, W1, asw1, adw1, n);
    k_gat1<<<(n + 7) / 8, 256>>>(b1, n);
    k_gemm2<<<(n + 127) / 128, 256>>>(W2, asw2, adw2, n);
    k_gat2<<<(n + 7) / 8, 256>>>(b2, batch, n);
    k_final<<<1, GG * NCLS>>>(Wlin, blin, out);
}